// round 14
// baseline (speedup 1.0000x reference)
#include <cuda_runtime.h>
#include <cuda_fp16.h>
#include <cstdint>

#define NN 100000
#define NF 512
#define NH 256
#define NC 40
#define NE 1600000
#define KH 10

// ---------------- scratch (device globals; no allocations allowed) ----------
__device__ float  g_H1[(size_t)NN * NH];   // hidden activations (102.4 MB)
__device__ float4 g_q0[NN * 10];           // q = d*h, ping      (16 MB)
__device__ float4 g_q1[NN * 10];           // q pong             (16 MB)
__device__ float4 g_TH[NN * 10];           // accumulated logits (16 MB)
__device__ int    g_deg[NN];
__device__ float  g_d[NN];
__device__ int    g_rowptr[NN + 1];
__device__ int    g_cursor[NN];
__device__ int    g_col[NE];
// W1 split to fp16 hi/lo, transposed to [n=256][k=512] (k contiguous)
__device__ __align__(16) __half g_Bhi[NH * NF];
__device__ __align__(16) __half g_Blo[NH * NF];

// ---------------- graph preprocessing ---------------------------------------
__global__ void zero_deg_kernel() {
    int v = blockIdx.x * blockDim.x + threadIdx.x;
    if (v < NN) g_deg[v] = 0;
}
__global__ void count_deg_kernel(const int* __restrict__ dst) {
    int e = blockIdx.x * blockDim.x + threadIdx.x;
    if (e < NE) atomicAdd(&g_deg[dst[e]], 1);
}
__global__ void scan_kernel() {
    const int T = 1024;
    int tid = threadIdx.x;
    const int per = (NN + T - 1) / T;
    int base = tid * per;
    int s = 0;
    for (int i = 0; i < per; i++) {
        int v = base + i;
        if (v < NN) s += g_deg[v];
    }
    __shared__ int sm[T];
    sm[tid] = s;
    __syncthreads();
    for (int off = 1; off < T; off <<= 1) {
        int add = (tid >= off) ? sm[tid - off] : 0;
        __syncthreads();
        sm[tid] += add;
        __syncthreads();
    }
    int run = sm[tid] - s;
    for (int i = 0; i < per; i++) {
        int v = base + i;
        if (v < NN) {
            int dv = g_deg[v];
            g_rowptr[v] = run;
            g_cursor[v] = run;
            g_d[v] = rsqrtf((float)(dv + 1));
            run += dv;
        }
    }
    if (tid == T - 1) g_rowptr[NN] = run;
}
__global__ void scatter_kernel(const int* __restrict__ src, const int* __restrict__ dst) {
    int e = blockIdx.x * blockDim.x + threadIdx.x;
    if (e < NE) {
        int v = dst[e];
        int p = atomicAdd(&g_cursor[v], 1);
        g_col[p] = src[e];
    }
}

// ---------------- W1 -> transposed fp16 hi/lo images -------------------------
__global__ void prep_w1_kernel(const float* __restrict__ W1) {
    int t = blockIdx.x * blockDim.x + threadIdx.x;
    if (t >= NH * NF) return;
    int k = t & (NF - 1);
    int n = t >> 9;
    float x = W1[(size_t)k * NH + n];
    __half h = __float2half_rn(x);
    float lo = x - __half2float(h);
    g_Bhi[(size_t)n * NF + k] = h;
    g_Blo[(size_t)n * NF + k] = __float2half_rn(lo);
}

// ---------------- GEMM1 on mma.sync fp16 (2-pass asymmetric split) ----------
// H1 = relu(feat @ W1 + b1). CTA 128(M) x 128(N), BK=32, 8 warps @ 64x32.
#define BK 32
#define RSTR 20  // smem row stride in uints (80 B): conflict-free frag loads

__device__ __forceinline__ void mma16816(float* c, const uint32_t* a, const uint32_t* b) {
    asm volatile(
        "mma.sync.aligned.m16n8k16.row.col.f32.f16.f16.f32 "
        "{%0,%1,%2,%3}, {%4,%5,%6,%7}, {%8,%9}, {%0,%1,%2,%3};"
        : "+f"(c[0]), "+f"(c[1]), "+f"(c[2]), "+f"(c[3])
        : "r"(a[0]), "r"(a[1]), "r"(a[2]), "r"(a[3]), "r"(b[0]), "r"(b[1]));
}

__global__ __launch_bounds__(256, 2) void gemm1_mma_kernel(const float* __restrict__ A,
                                                           const float* __restrict__ bias) {
    __shared__ uint32_t sA [128 * RSTR];
    __shared__ uint32_t sBh[128 * RSTR];
    __shared__ uint32_t sBl[128 * RSTR];

    const int tid = threadIdx.x;
    const int wid = tid >> 5, lane = tid & 31;
    const int wm = wid >> 2, wn = wid & 3;        // warp tile: (wm*64, wn*32)
    const int m0 = blockIdx.y * 128;
    const int col0 = blockIdx.x * 128;

    float acc[4][4][4];
#pragma unroll
    for (int i = 0; i < 4; i++)
#pragma unroll
        for (int j = 0; j < 4; j++)
#pragma unroll
            for (int e = 0; e < 4; e++) acc[i][j][e] = 0.f;

    // per-thread staging indices: row lr = tid>>1, k-half seg = tid&1 (16 elems)
    const int lr = tid >> 1, seg = tid & 1;
    const int gr = m0 + lr;
    const bool avalid = gr < NN;
    const float* Arow = A + (size_t)gr * NF + seg * 16;
    const __half* BHrow = g_Bhi + (size_t)(col0 + lr) * NF + seg * 16;
    const __half* BLrow = g_Blo + (size_t)(col0 + lr) * NF + seg * 16;
    const int sbase = lr * RSTR + seg * 8;

    for (int kc = 0; kc < NF / BK; kc++) {
        __syncthreads();
        // ---- stage A: fp32 -> fp16 (single rounding)
        {
            float vals[16];
            if (avalid) {
#pragma unroll
                for (int q = 0; q < 4; q++) {
                    float4 v = *(const float4*)(Arow + kc * BK + q * 4);
                    vals[q * 4 + 0] = v.x; vals[q * 4 + 1] = v.y;
                    vals[q * 4 + 2] = v.z; vals[q * 4 + 3] = v.w;
                }
            } else {
#pragma unroll
                for (int q = 0; q < 16; q++) vals[q] = 0.f;
            }
            uint32_t hu[8];
#pragma unroll
            for (int p = 0; p < 8; p++) {
                __half h0 = __float2half_rn(vals[2 * p]);
                __half h1 = __float2half_rn(vals[2 * p + 1]);
                hu[p] = (uint32_t)__half_as_ushort(h0) |
                        ((uint32_t)__half_as_ushort(h1) << 16);
            }
            *(uint4*)&sA[sbase]     = make_uint4(hu[0], hu[1], hu[2], hu[3]);
            *(uint4*)&sA[sbase + 4] = make_uint4(hu[4], hu[5], hu[6], hu[7]);
        }
        // ---- stage B: copy pre-split fp16 (L2-hot)
        {
            const uint4* ph = (const uint4*)(BHrow + kc * BK);
            const uint4* pl = (const uint4*)(BLrow + kc * BK);
            *(uint4*)&sBh[sbase]     = ph[0];
            *(uint4*)&sBh[sbase + 4] = ph[1];
            *(uint4*)&sBl[sbase]     = pl[0];
            *(uint4*)&sBl[sbase + 4] = pl[1];
        }
        __syncthreads();

        // ---- compute: 2 k16 steps x 2 passes (A x Bhi, A x Blo); A frags reused
#pragma unroll
        for (int k16 = 0; k16 < 2; k16++) {
            uint32_t af[4][4];
#pragma unroll
            for (int mt = 0; mt < 4; mt++) {
                int r = wm * 64 + mt * 16 + (lane >> 2);
                int b = r * RSTR + k16 * 8 + (lane & 3);
                af[mt][0] = sA[b];
                af[mt][1] = sA[b + 8 * RSTR];
                af[mt][2] = sA[b + 4];
                af[mt][3] = sA[b + 8 * RSTR + 4];
            }
            uint32_t bf_[4][2];
#pragma unroll
            for (int nt = 0; nt < 4; nt++) {
                int n = wn * 32 + nt * 8 + (lane >> 2);
                int b = n * RSTR + k16 * 8 + (lane & 3);
                bf_[nt][0] = sBh[b];
                bf_[nt][1] = sBh[b + 4];
            }
#pragma unroll
            for (int mt = 0; mt < 4; mt++)
#pragma unroll
                for (int nt = 0; nt < 4; nt++)
                    mma16816(acc[mt][nt], af[mt], bf_[nt]);
#pragma unroll
            for (int nt = 0; nt < 4; nt++) {
                int n = wn * 32 + nt * 8 + (lane >> 2);
                int b = n * RSTR + k16 * 8 + (lane & 3);
                bf_[nt][0] = sBl[b];
                bf_[nt][1] = sBl[b + 4];
            }
#pragma unroll
            for (int mt = 0; mt < 4; mt++)
#pragma unroll
                for (int nt = 0; nt < 4; nt++)
                    mma16816(acc[mt][nt], af[mt], bf_[nt]);
        }
    }

    // ---- epilogue: bias + relu, store fp32
#pragma unroll
    for (int nt = 0; nt < 4; nt++) {
        int cg = col0 + wn * 32 + nt * 8 + 2 * (lane & 3);
        float b0 = bias[cg], b1 = bias[cg + 1];
#pragma unroll
        for (int mt = 0; mt < 4; mt++) {
            int r0 = m0 + wm * 64 + mt * 16 + (lane >> 2);
            if (r0 < NN) {
                float2 o;
                o.x = fmaxf(acc[mt][nt][0] + b0, 0.f);
                o.y = fmaxf(acc[mt][nt][1] + b1, 0.f);
                *(float2*)(g_H1 + (size_t)r0 * NH + cg) = o;
            }
            int r1 = r0 + 8;
            if (r1 < NN) {
                float2 o;
                o.x = fmaxf(acc[mt][nt][2] + b0, 0.f);
                o.y = fmaxf(acc[mt][nt][3] + b1, 0.f);
                *(float2*)(g_H1 + (size_t)r1 * NH + cg) = o;
            }
        }
    }
}

// ---------------- GEMM2 + epilogue: h = H1 @ W2 + b2; q0 = d*h; TH = t0*h ---
__global__ __launch_bounds__(256) void gemm2_kernel(const float* __restrict__ W2,
                                                    const float* __restrict__ b2,
                                                    const float* __restrict__ temp) {
    __shared__ float4 W2s[NH * 10];
    __shared__ float  b2s[NC];
    int tid = threadIdx.x;
    for (int i = tid; i < NH * 10; i += 256) W2s[i] = ((const float4*)W2)[i];
    if (tid < NC) b2s[tid] = b2[tid];
    __syncthreads();

    int v = blockIdx.x * 256 + tid;
    if (v >= NN) return;

    float acc[NC];
#pragma unroll
    for (int c = 0; c < NC; c++) acc[c] = 0.f;

    const float4* hrow = (const float4*)(g_H1 + (size_t)v * NH);
#pragma unroll 2
    for (int k4 = 0; k4 < NH / 4; k4++) {
        float4 a = hrow[k4];
        const float4* wr = &W2s[(k4 * 4) * 10];
        float av[4] = {a.x, a.y, a.z, a.w};
#pragma unroll
        for (int kk = 0; kk < 4; kk++) {
#pragma unroll
            for (int c4 = 0; c4 < 10; c4++) {
                float4 w = wr[kk * 10 + c4];
                acc[c4 * 4 + 0] += av[kk] * w.x;
                acc[c4 * 4 + 1] += av[kk] * w.y;
                acc[c4 * 4 + 2] += av[kk] * w.z;
                acc[c4 * 4 + 3] += av[kk] * w.w;
            }
        }
    }

    float dv = g_d[v];
    float t0 = temp[0];
    float4* qrow = g_q0 + v * 10;
    float4* trow = g_TH + v * 10;
#pragma unroll
    for (int c4 = 0; c4 < 10; c4++) {
        float hx = acc[c4 * 4 + 0] + b2s[c4 * 4 + 0];
        float hy = acc[c4 * 4 + 1] + b2s[c4 * 4 + 1];
        float hz = acc[c4 * 4 + 2] + b2s[c4 * 4 + 2];
        float hw = acc[c4 * 4 + 3] + b2s[c4 * 4 + 3];
        qrow[c4] = make_float4(dv * hx, dv * hy, dv * hz, dv * hw);
        trow[c4] = make_float4(t0 * hx, t0 * hy, t0 * hz, t0 * hw);
    }
}

// ---------------- one propagation hop ---------------------------------------
__global__ void hop_kernel(const float* __restrict__ temp, int hop) {
    int t  = blockIdx.x * blockDim.x + threadIdx.x;
    int v  = t >> 4;
    int c4 = t & 15;
    if (v >= NN || c4 >= 10) return;

    const float4* qin = (hop & 1) ? g_q1 : g_q0;
    float4*       qout = (hop & 1) ? g_q0 : g_q1;

    int rs = g_rowptr[v];
    int re = g_rowptr[v + 1];
    float4 acc = qin[v * 10 + c4];

    int i = rs;
    for (; i + 1 < re; i += 2) {
        int u0 = g_col[i];
        int u1 = g_col[i + 1];
        float4 x0 = qin[u0 * 10 + c4];
        float4 x1 = qin[u1 * 10 + c4];
        acc.x += x0.x; acc.y += x0.y; acc.z += x0.z; acc.w += x0.w;
        acc.x += x1.x; acc.y += x1.y; acc.z += x1.z; acc.w += x1.w;
    }
    if (i < re) {
        int u = g_col[i];
        float4 x = qin[u * 10 + c4];
        acc.x += x.x; acc.y += x.y; acc.z += x.z; acc.w += x.w;
    }

    float dv = g_d[v];
    float tk = temp[hop + 1];
    float dd = dv * dv;
    float td = tk * dv;

    qout[v * 10 + c4] = make_float4(dd * acc.x, dd * acc.y, dd * acc.z, dd * acc.w);
    float4 th = g_TH[v * 10 + c4];
    g_TH[v * 10 + c4] = make_float4(th.x + td * acc.x, th.y + td * acc.y,
                                    th.z + td * acc.z, th.w + td * acc.w);
}

// ---------------- log_softmax epilogue ---------------------------------------
__global__ void final_kernel(float* __restrict__ out) {
    int v = blockIdx.x * blockDim.x + threadIdx.x;
    if (v >= NN) return;
    float th[NC];
    const float4* trow = g_TH + v * 10;
#pragma unroll
    for (int c4 = 0; c4 < 10; c4++) {
        float4 x = trow[c4];
        th[c4 * 4 + 0] = x.x;
        th[c4 * 4 + 1] = x.y;
        th[c4 * 4 + 2] = x.z;
        th[c4 * 4 + 3] = x.w;
    }
    float m = th[0];
#pragma unroll
    for (int c = 1; c < NC; c++) m = fmaxf(m, th[c]);
    float s = 0.f;
#pragma unroll
    for (int c = 0; c < NC; c++) s += __expf(th[c] - m);
    float lse = m + logf(s);
    float4* orow = (float4*)(out + (size_t)v * NC);
#pragma unroll
    for (int c4 = 0; c4 < 10; c4++) {
        orow[c4] = make_float4(th[c4 * 4 + 0] - lse, th[c4 * 4 + 1] - lse,
                               th[c4 * 4 + 2] - lse, th[c4 * 4 + 3] - lse);
    }
}

// ---------------- launch -----------------------------------------------------
extern "C" void kernel_launch(void* const* d_in, const int* in_sizes, int n_in,
                              void* d_out, int out_size) {
    (void)in_sizes; (void)n_in; (void)out_size;
    const float* feat = (const float*)d_in[0];
    const float* W1   = (const float*)d_in[1];
    const float* b1   = (const float*)d_in[2];
    const float* W2   = (const float*)d_in[3];
    const float* b2   = (const float*)d_in[4];
    const float* temp = (const float*)d_in[5];
    const int*   src  = (const int*)d_in[6];
    const int*   dst  = (const int*)d_in[7];
    float* out = (float*)d_out;

    zero_deg_kernel<<<(NN + 255) / 256, 256>>>();
    count_deg_kernel<<<(NE + 255) / 256, 256>>>(dst);
    scan_kernel<<<1, 1024>>>();
    scatter_kernel<<<(NE + 255) / 256, 256>>>(src, dst);

    prep_w1_kernel<<<(NH * NF + 255) / 256, 256>>>(W1);
    gemm1_mma_kernel<<<dim3(NH / 128, (NN + 127) / 128), 256>>>(feat, b1);
    gemm2_kernel<<<(NN + 255) / 256, 256>>>(W2, b2, temp);

    for (int k = 0; k < KH; k++) {
        hop_kernel<<<(NN * 16 + 255) / 256, 256>>>(temp, k);
    }

    final_kernel<<<(NN + 255) / 256, 256>>>(out);
}

// round 15
// speedup vs baseline: 1.0295x; 1.0295x over previous
#include <cuda_runtime.h>
#include <cuda_fp16.h>
#include <cstdint>

#define NN 100000
#define NF 512
#define NH 256
#define NC 40
#define NE 1600000
#define KH 10

// ---------------- scratch (device globals; no allocations allowed) ----------
__device__ float  g_H1[(size_t)NN * NH];   // hidden activations (102.4 MB)
__device__ float4 g_q0[NN * 10];           // q = d*h, ping      (16 MB)
__device__ float4 g_q1[NN * 10];           // q pong             (16 MB)
__device__ float4 g_TH[NN * 10];           // accumulated logits (16 MB)
__device__ int    g_deg[NN];
__device__ float  g_d[NN];
__device__ int    g_rowptr[NN + 1];
__device__ int    g_cursor[NN];
__device__ int    g_col[NE];
// W1 split to fp16 hi/lo, transposed to [n=256][k=512] (k contiguous)
__device__ __align__(16) __half g_Bhi[NH * NF];
__device__ __align__(16) __half g_Blo[NH * NF];

// ---------------- graph preprocessing ---------------------------------------
__global__ void zero_deg_kernel() {
    int v = blockIdx.x * blockDim.x + threadIdx.x;
    if (v < NN) g_deg[v] = 0;
}
__global__ void count_deg_kernel(const int* __restrict__ dst) {
    int e = blockIdx.x * blockDim.x + threadIdx.x;
    if (e < NE) atomicAdd(&g_deg[dst[e]], 1);
}
__global__ void scan_kernel() {
    const int T = 1024;
    int tid = threadIdx.x;
    const int per = (NN + T - 1) / T;
    int base = tid * per;
    int s = 0;
    for (int i = 0; i < per; i++) {
        int v = base + i;
        if (v < NN) s += g_deg[v];
    }
    __shared__ int sm[T];
    sm[tid] = s;
    __syncthreads();
    for (int off = 1; off < T; off <<= 1) {
        int add = (tid >= off) ? sm[tid - off] : 0;
        __syncthreads();
        sm[tid] += add;
        __syncthreads();
    }
    int run = sm[tid] - s;
    for (int i = 0; i < per; i++) {
        int v = base + i;
        if (v < NN) {
            int dv = g_deg[v];
            g_rowptr[v] = run;
            g_cursor[v] = run;
            g_d[v] = rsqrtf((float)(dv + 1));
            run += dv;
        }
    }
    if (tid == T - 1) g_rowptr[NN] = run;
}
__global__ void scatter_kernel(const int* __restrict__ src, const int* __restrict__ dst) {
    int e = blockIdx.x * blockDim.x + threadIdx.x;
    if (e < NE) {
        int v = dst[e];
        int p = atomicAdd(&g_cursor[v], 1);
        g_col[p] = src[e];
    }
}

// ---------------- W1 -> transposed fp16 hi/lo images -------------------------
__global__ void prep_w1_kernel(const float* __restrict__ W1) {
    int t = blockIdx.x * blockDim.x + threadIdx.x;
    if (t >= NH * NF) return;
    int k = t & (NF - 1);
    int n = t >> 9;
    float x = W1[(size_t)k * NH + n];
    __half h = __float2half_rn(x);
    float lo = x - __half2float(h);
    g_Bhi[(size_t)n * NF + k] = h;
    g_Blo[(size_t)n * NF + k] = __float2half_rn(lo);
}

// ---------------- GEMM1 on mma.sync fp16 (2-pass asymmetric split) ----------
// H1 = relu(feat @ W1 + b1). CTA 128(M) x 128(N), BK=32, 8 warps @ 64x32.
#define BK 32
#define RSTR 20  // smem row stride in uints (80 B): conflict-free frag loads

__device__ __forceinline__ void mma16816(float* c, const uint32_t* a, const uint32_t* b) {
    asm volatile(
        "mma.sync.aligned.m16n8k16.row.col.f32.f16.f16.f32 "
        "{%0,%1,%2,%3}, {%4,%5,%6,%7}, {%8,%9}, {%0,%1,%2,%3};"
        : "+f"(c[0]), "+f"(c[1]), "+f"(c[2]), "+f"(c[3])
        : "r"(a[0]), "r"(a[1]), "r"(a[2]), "r"(a[3]), "r"(b[0]), "r"(b[1]));
}

__global__ __launch_bounds__(256, 2) void gemm1_mma_kernel(const float* __restrict__ A,
                                                           const float* __restrict__ bias) {
    __shared__ uint32_t sA [128 * RSTR];
    __shared__ uint32_t sBh[128 * RSTR];
    __shared__ uint32_t sBl[128 * RSTR];

    const int tid = threadIdx.x;
    const int wid = tid >> 5, lane = tid & 31;
    const int wm = wid >> 2, wn = wid & 3;        // warp tile: (wm*64, wn*32)
    const int m0 = blockIdx.y * 128;
    const int col0 = blockIdx.x * 128;

    float acc[4][4][4];
#pragma unroll
    for (int i = 0; i < 4; i++)
#pragma unroll
        for (int j = 0; j < 4; j++)
#pragma unroll
            for (int e = 0; e < 4; e++) acc[i][j][e] = 0.f;

    // per-thread staging indices: row lr = tid>>1, k-half seg = tid&1 (16 elems)
    const int lr = tid >> 1, seg = tid & 1;
    const int gr = m0 + lr;
    const bool avalid = gr < NN;
    const float* Arow = A + (size_t)gr * NF + seg * 16;
    const __half* BHrow = g_Bhi + (size_t)(col0 + lr) * NF + seg * 16;
    const __half* BLrow = g_Blo + (size_t)(col0 + lr) * NF + seg * 16;
    const int sbase = lr * RSTR + seg * 8;

    for (int kc = 0; kc < NF / BK; kc++) {
        __syncthreads();
        // ---- stage A: fp32 -> fp16 (single rounding)
        {
            float vals[16];
            if (avalid) {
#pragma unroll
                for (int q = 0; q < 4; q++) {
                    float4 v = *(const float4*)(Arow + kc * BK + q * 4);
                    vals[q * 4 + 0] = v.x; vals[q * 4 + 1] = v.y;
                    vals[q * 4 + 2] = v.z; vals[q * 4 + 3] = v.w;
                }
            } else {
#pragma unroll
                for (int q = 0; q < 16; q++) vals[q] = 0.f;
            }
            uint32_t hu[8];
#pragma unroll
            for (int p = 0; p < 8; p++) {
                __half h0 = __float2half_rn(vals[2 * p]);
                __half h1 = __float2half_rn(vals[2 * p + 1]);
                hu[p] = (uint32_t)__half_as_ushort(h0) |
                        ((uint32_t)__half_as_ushort(h1) << 16);
            }
            *(uint4*)&sA[sbase]     = make_uint4(hu[0], hu[1], hu[2], hu[3]);
            *(uint4*)&sA[sbase + 4] = make_uint4(hu[4], hu[5], hu[6], hu[7]);
        }
        // ---- stage B: copy pre-split fp16 (L2-hot)
        {
            const uint4* ph = (const uint4*)(BHrow + kc * BK);
            const uint4* pl = (const uint4*)(BLrow + kc * BK);
            *(uint4*)&sBh[sbase]     = ph[0];
            *(uint4*)&sBh[sbase + 4] = ph[1];
            *(uint4*)&sBl[sbase]     = pl[0];
            *(uint4*)&sBl[sbase + 4] = pl[1];
        }
        __syncthreads();

        // ---- compute: 2 k16 steps x 2 passes (A x Bhi, A x Blo); A frags reused
#pragma unroll
        for (int k16 = 0; k16 < 2; k16++) {
            uint32_t af[4][4];
#pragma unroll
            for (int mt = 0; mt < 4; mt++) {
                int r = wm * 64 + mt * 16 + (lane >> 2);
                int b = r * RSTR + k16 * 8 + (lane & 3);
                af[mt][0] = sA[b];
                af[mt][1] = sA[b + 8 * RSTR];
                af[mt][2] = sA[b + 4];
                af[mt][3] = sA[b + 8 * RSTR + 4];
            }
            uint32_t bf_[4][2];
#pragma unroll
            for (int nt = 0; nt < 4; nt++) {
                int n = wn * 32 + nt * 8 + (lane >> 2);
                int b = n * RSTR + k16 * 8 + (lane & 3);
                bf_[nt][0] = sBh[b];
                bf_[nt][1] = sBh[b + 4];
            }
#pragma unroll
            for (int mt = 0; mt < 4; mt++)
#pragma unroll
                for (int nt = 0; nt < 4; nt++)
                    mma16816(acc[mt][nt], af[mt], bf_[nt]);
#pragma unroll
            for (int nt = 0; nt < 4; nt++) {
                int n = wn * 32 + nt * 8 + (lane >> 2);
                int b = n * RSTR + k16 * 8 + (lane & 3);
                bf_[nt][0] = sBl[b];
                bf_[nt][1] = sBl[b + 4];
            }
#pragma unroll
            for (int mt = 0; mt < 4; mt++)
#pragma unroll
                for (int nt = 0; nt < 4; nt++)
                    mma16816(acc[mt][nt], af[mt], bf_[nt]);
        }
    }

    // ---- epilogue: bias + relu, store fp32
#pragma unroll
    for (int nt = 0; nt < 4; nt++) {
        int cg = col0 + wn * 32 + nt * 8 + 2 * (lane & 3);
        float b0 = bias[cg], b1 = bias[cg + 1];
#pragma unroll
        for (int mt = 0; mt < 4; mt++) {
            int r0 = m0 + wm * 64 + mt * 16 + (lane >> 2);
            if (r0 < NN) {
                float2 o;
                o.x = fmaxf(acc[mt][nt][0] + b0, 0.f);
                o.y = fmaxf(acc[mt][nt][1] + b1, 0.f);
                *(float2*)(g_H1 + (size_t)r0 * NH + cg) = o;
            }
            int r1 = r0 + 8;
            if (r1 < NN) {
                float2 o;
                o.x = fmaxf(acc[mt][nt][2] + b0, 0.f);
                o.y = fmaxf(acc[mt][nt][3] + b1, 0.f);
                *(float2*)(g_H1 + (size_t)r1 * NH + cg) = o;
            }
        }
    }
}

// ---------------- GEMM2 + epilogue: h = H1 @ W2 + b2; q0 = d*h; TH = t0*h ---
__global__ __launch_bounds__(256) void gemm2_kernel(const float* __restrict__ W2,
                                                    const float* __restrict__ b2,
                                                    const float* __restrict__ temp) {
    __shared__ float4 W2s[NH * 10];
    __shared__ float  b2s[NC];
    int tid = threadIdx.x;
    for (int i = tid; i < NH * 10; i += 256) W2s[i] = ((const float4*)W2)[i];
    if (tid < NC) b2s[tid] = b2[tid];
    __syncthreads();

    int v = blockIdx.x * 256 + tid;
    if (v >= NN) return;

    float acc[NC];
#pragma unroll
    for (int c = 0; c < NC; c++) acc[c] = 0.f;

    const float4* hrow = (const float4*)(g_H1 + (size_t)v * NH);
#pragma unroll 2
    for (int k4 = 0; k4 < NH / 4; k4++) {
        float4 a = hrow[k4];
        const float4* wr = &W2s[(k4 * 4) * 10];
        float av[4] = {a.x, a.y, a.z, a.w};
#pragma unroll
        for (int kk = 0; kk < 4; kk++) {
#pragma unroll
            for (int c4 = 0; c4 < 10; c4++) {
                float4 w = wr[kk * 10 + c4];
                acc[c4 * 4 + 0] += av[kk] * w.x;
                acc[c4 * 4 + 1] += av[kk] * w.y;
                acc[c4 * 4 + 2] += av[kk] * w.z;
                acc[c4 * 4 + 3] += av[kk] * w.w;
            }
        }
    }

    float dv = g_d[v];
    float t0 = temp[0];
    float4* qrow = g_q0 + v * 10;
    float4* trow = g_TH + v * 10;
#pragma unroll
    for (int c4 = 0; c4 < 10; c4++) {
        float hx = acc[c4 * 4 + 0] + b2s[c4 * 4 + 0];
        float hy = acc[c4 * 4 + 1] + b2s[c4 * 4 + 1];
        float hz = acc[c4 * 4 + 2] + b2s[c4 * 4 + 2];
        float hw = acc[c4 * 4 + 3] + b2s[c4 * 4 + 3];
        qrow[c4] = make_float4(dv * hx, dv * hy, dv * hz, dv * hw);
        trow[c4] = make_float4(t0 * hx, t0 * hy, t0 * hz, t0 * hw);
    }
}

// ---------------- one propagation hop ---------------------------------------
__global__ void hop_kernel(const float* __restrict__ temp, int hop) {
    int t  = blockIdx.x * blockDim.x + threadIdx.x;
    int v  = t >> 4;
    int c4 = t & 15;
    if (v >= NN || c4 >= 10) return;

    const float4* qin = (hop & 1) ? g_q1 : g_q0;
    float4*       qout = (hop & 1) ? g_q0 : g_q1;

    int rs = g_rowptr[v];
    int re = g_rowptr[v + 1];
    float4 acc = qin[v * 10 + c4];

    int i = rs;
    for (; i + 1 < re; i += 2) {
        int u0 = g_col[i];
        int u1 = g_col[i + 1];
        float4 x0 = qin[u0 * 10 + c4];
        float4 x1 = qin[u1 * 10 + c4];
        acc.x += x0.x; acc.y += x0.y; acc.z += x0.z; acc.w += x0.w;
        acc.x += x1.x; acc.y += x1.y; acc.z += x1.z; acc.w += x1.w;
    }
    if (i < re) {
        int u = g_col[i];
        float4 x = qin[u * 10 + c4];
        acc.x += x.x; acc.y += x.y; acc.z += x.z; acc.w += x.w;
    }

    float dv = g_d[v];
    float tk = temp[hop + 1];
    float dd = dv * dv;
    float td = tk * dv;

    qout[v * 10 + c4] = make_float4(dd * acc.x, dd * acc.y, dd * acc.z, dd * acc.w);
    float4 th = g_TH[v * 10 + c4];
    g_TH[v * 10 + c4] = make_float4(th.x + td * acc.x, th.y + td * acc.y,
                                    th.z + td * acc.z, th.w + td * acc.w);
}

// ---------------- log_softmax epilogue ---------------------------------------
__global__ void final_kernel(float* __restrict__ out) {
    int v = blockIdx.x * blockDim.x + threadIdx.x;
    if (v >= NN) return;
    float th[NC];
    const float4* trow = g_TH + v * 10;
#pragma unroll
    for (int c4 = 0; c4 < 10; c4++) {
        float4 x = trow[c4];
        th[c4 * 4 + 0] = x.x;
        th[c4 * 4 + 1] = x.y;
        th[c4 * 4 + 2] = x.z;
        th[c4 * 4 + 3] = x.w;
    }
    float m = th[0];
#pragma unroll
    for (int c = 1; c < NC; c++) m = fmaxf(m, th[c]);
    float s = 0.f;
#pragma unroll
    for (int c = 0; c < NC; c++) s += __expf(th[c] - m);
    float lse = m + logf(s);
    float4* orow = (float4*)(out + (size_t)v * NC);
#pragma unroll
    for (int c4 = 0; c4 < 10; c4++) {
        orow[c4] = make_float4(th[c4 * 4 + 0] - lse, th[c4 * 4 + 1] - lse,
                               th[c4 * 4 + 2] - lse, th[c4 * 4 + 3] - lse);
    }
}

// ---------------- launch -----------------------------------------------------
extern "C" void kernel_launch(void* const* d_in, const int* in_sizes, int n_in,
                              void* d_out, int out_size) {
    (void)in_sizes; (void)n_in; (void)out_size;
    const float* feat = (const float*)d_in[0];
    const float* W1   = (const float*)d_in[1];
    const float* b1   = (const float*)d_in[2];
    const float* W2   = (const float*)d_in[3];
    const float* b2   = (const float*)d_in[4];
    const float* temp = (const float*)d_in[5];
    const int*   src  = (const int*)d_in[6];
    const int*   dst  = (const int*)d_in[7];
    float* out = (float*)d_out;

    zero_deg_kernel<<<(NN + 255) / 256, 256>>>();
    count_deg_kernel<<<(NE + 255) / 256, 256>>>(dst);
    scan_kernel<<<1, 1024>>>();
    scatter_kernel<<<(NE + 255) / 256, 256>>>(src, dst);

    prep_w1_kernel<<<(NH * NF + 255) / 256, 256>>>(W1);
    gemm1_mma_kernel<<<dim3(NH / 128, (NN + 127) / 128), 256>>>(feat, b1);
    gemm2_kernel<<<(NN + 255) / 256, 256>>>(W2, b2, temp);

    for (int k = 0; k < KH; k++) {
        hop_kernel<<<(NN * 16 + 255) / 256, 256>>>(temp, k);
    }

    final_kernel<<<(NN + 255) / 256, 256>>>(out);
}

// round 16
// speedup vs baseline: 1.0327x; 1.0031x over previous
#include <cuda_runtime.h>
#include <cuda_fp16.h>
#include <cstdint>

#define NN 100000
#define NF 512
#define NH 256
#define NC 40
#define NE 1600000
#define KH 10

// ---------------- scratch (device globals; no allocations allowed) ----------
__device__ float  g_H1[(size_t)NN * NH];   // hidden activations (102.4 MB)
__device__ float4 g_q0[NN * 10];           // q = d*h, ping      (16 MB)
__device__ float4 g_q1[NN * 10];           // q pong             (16 MB)
__device__ float4 g_TH[NN * 10];           // accumulated logits (16 MB)
__device__ int    g_deg[NN];
__device__ float  g_d[NN];
__device__ int    g_rowptr[NN + 1];
__device__ int    g_cursor[NN];
__device__ int    g_col[NE];
// W1 split to fp16 hi/lo, transposed to [n=256][k=512] (k contiguous)
__device__ __align__(16) __half g_Bhi[NH * NF];
__device__ __align__(16) __half g_Blo[NH * NF];

// ---------------- graph preprocessing ---------------------------------------
__global__ void zero_deg_kernel() {
    int v = blockIdx.x * blockDim.x + threadIdx.x;
    if (v < NN) g_deg[v] = 0;
}
__global__ void count_deg_kernel(const int* __restrict__ dst) {
    int e = blockIdx.x * blockDim.x + threadIdx.x;
    if (e < NE) atomicAdd(&g_deg[dst[e]], 1);
}
__global__ void scan_kernel() {
    const int T = 1024;
    int tid = threadIdx.x;
    const int per = (NN + T - 1) / T;
    int base = tid * per;
    int s = 0;
    for (int i = 0; i < per; i++) {
        int v = base + i;
        if (v < NN) s += g_deg[v];
    }
    __shared__ int sm[T];
    sm[tid] = s;
    __syncthreads();
    for (int off = 1; off < T; off <<= 1) {
        int add = (tid >= off) ? sm[tid - off] : 0;
        __syncthreads();
        sm[tid] += add;
        __syncthreads();
    }
    int run = sm[tid] - s;
    for (int i = 0; i < per; i++) {
        int v = base + i;
        if (v < NN) {
            int dv = g_deg[v];
            g_rowptr[v] = run;
            g_cursor[v] = run;
            g_d[v] = rsqrtf((float)(dv + 1));
            run += dv;
        }
    }
    if (tid == T - 1) g_rowptr[NN] = run;
}
__global__ void scatter_kernel(const int* __restrict__ src, const int* __restrict__ dst) {
    int e = blockIdx.x * blockDim.x + threadIdx.x;
    if (e < NE) {
        int v = dst[e];
        int p = atomicAdd(&g_cursor[v], 1);
        g_col[p] = src[e];
    }
}

// ---------------- W1 -> transposed fp16 hi/lo images -------------------------
__global__ void prep_w1_kernel(const float* __restrict__ W1) {
    int t = blockIdx.x * blockDim.x + threadIdx.x;
    if (t >= NH * NF) return;
    int k = t & (NF - 1);
    int n = t >> 9;
    float x = W1[(size_t)k * NH + n];
    __half h = __float2half_rn(x);
    float lo = x - __half2float(h);
    g_Bhi[(size_t)n * NF + k] = h;
    g_Blo[(size_t)n * NF + k] = __float2half_rn(lo);
}

// ---------------- GEMM1 on mma.sync fp16 (2-pass asymmetric split) ----------
// H1 = relu(feat @ W1 + b1). CTA 128(M) x 128(N), BK=32, 8 warps @ 64x32.
#define BK 32
#define RSTR 20  // smem row stride in uints (80 B): conflict-free frag loads

__device__ __forceinline__ void mma16816(float* c, const uint32_t* a, const uint32_t* b) {
    asm volatile(
        "mma.sync.aligned.m16n8k16.row.col.f32.f16.f16.f32 "
        "{%0,%1,%2,%3}, {%4,%5,%6,%7}, {%8,%9}, {%0,%1,%2,%3};"
        : "+f"(c[0]), "+f"(c[1]), "+f"(c[2]), "+f"(c[3])
        : "r"(a[0]), "r"(a[1]), "r"(a[2]), "r"(a[3]), "r"(b[0]), "r"(b[1]));
}

__global__ __launch_bounds__(256, 2) void gemm1_mma_kernel(const float* __restrict__ A,
                                                           const float* __restrict__ bias) {
    __shared__ uint32_t sA [128 * RSTR];
    __shared__ uint32_t sBh[128 * RSTR];
    __shared__ uint32_t sBl[128 * RSTR];

    const int tid = threadIdx.x;
    const int wid = tid >> 5, lane = tid & 31;
    const int wm = wid >> 2, wn = wid & 3;        // warp tile: (wm*64, wn*32)
    const int m0 = blockIdx.y * 128;
    const int col0 = blockIdx.x * 128;

    float acc[4][4][4];
#pragma unroll
    for (int i = 0; i < 4; i++)
#pragma unroll
        for (int j = 0; j < 4; j++)
#pragma unroll
            for (int e = 0; e < 4; e++) acc[i][j][e] = 0.f;

    // per-thread staging indices: row lr = tid>>1, k-half seg = tid&1 (16 elems)
    const int lr = tid >> 1, seg = tid & 1;
    const int gr = m0 + lr;
    const bool avalid = gr < NN;
    const float* Arow = A + (size_t)gr * NF + seg * 16;
    const __half* BHrow = g_Bhi + (size_t)(col0 + lr) * NF + seg * 16;
    const __half* BLrow = g_Blo + (size_t)(col0 + lr) * NF + seg * 16;
    const int sbase = lr * RSTR + seg * 8;

    for (int kc = 0; kc < NF / BK; kc++) {
        __syncthreads();
        // ---- stage A: fp32 -> fp16 (single rounding)
        {
            float vals[16];
            if (avalid) {
#pragma unroll
                for (int q = 0; q < 4; q++) {
                    float4 v = *(const float4*)(Arow + kc * BK + q * 4);
                    vals[q * 4 + 0] = v.x; vals[q * 4 + 1] = v.y;
                    vals[q * 4 + 2] = v.z; vals[q * 4 + 3] = v.w;
                }
            } else {
#pragma unroll
                for (int q = 0; q < 16; q++) vals[q] = 0.f;
            }
            uint32_t hu[8];
#pragma unroll
            for (int p = 0; p < 8; p++) {
                __half h0 = __float2half_rn(vals[2 * p]);
                __half h1 = __float2half_rn(vals[2 * p + 1]);
                hu[p] = (uint32_t)__half_as_ushort(h0) |
                        ((uint32_t)__half_as_ushort(h1) << 16);
            }
            *(uint4*)&sA[sbase]     = make_uint4(hu[0], hu[1], hu[2], hu[3]);
            *(uint4*)&sA[sbase + 4] = make_uint4(hu[4], hu[5], hu[6], hu[7]);
        }
        // ---- stage B: copy pre-split fp16 (L2-hot)
        {
            const uint4* ph = (const uint4*)(BHrow + kc * BK);
            const uint4* pl = (const uint4*)(BLrow + kc * BK);
            *(uint4*)&sBh[sbase]     = ph[0];
            *(uint4*)&sBh[sbase + 4] = ph[1];
            *(uint4*)&sBl[sbase]     = pl[0];
            *(uint4*)&sBl[sbase + 4] = pl[1];
        }
        __syncthreads();

        // ---- compute: 2 k16 steps x 2 passes (A x Bhi, A x Blo); A frags reused
#pragma unroll
        for (int k16 = 0; k16 < 2; k16++) {
            uint32_t af[4][4];
#pragma unroll
            for (int mt = 0; mt < 4; mt++) {
                int r = wm * 64 + mt * 16 + (lane >> 2);
                int b = r * RSTR + k16 * 8 + (lane & 3);
                af[mt][0] = sA[b];
                af[mt][1] = sA[b + 8 * RSTR];
                af[mt][2] = sA[b + 4];
                af[mt][3] = sA[b + 8 * RSTR + 4];
            }
            uint32_t bf_[4][2];
#pragma unroll
            for (int nt = 0; nt < 4; nt++) {
                int n = wn * 32 + nt * 8 + (lane >> 2);
                int b = n * RSTR + k16 * 8 + (lane & 3);
                bf_[nt][0] = sBh[b];
                bf_[nt][1] = sBh[b + 4];
            }
#pragma unroll
            for (int mt = 0; mt < 4; mt++)
#pragma unroll
                for (int nt = 0; nt < 4; nt++)
                    mma16816(acc[mt][nt], af[mt], bf_[nt]);
#pragma unroll
            for (int nt = 0; nt < 4; nt++) {
                int n = wn * 32 + nt * 8 + (lane >> 2);
                int b = n * RSTR + k16 * 8 + (lane & 3);
                bf_[nt][0] = sBl[b];
                bf_[nt][1] = sBl[b + 4];
            }
#pragma unroll
            for (int mt = 0; mt < 4; mt++)
#pragma unroll
                for (int nt = 0; nt < 4; nt++)
                    mma16816(acc[mt][nt], af[mt], bf_[nt]);
        }
    }

    // ---- epilogue: bias + relu, store fp32
#pragma unroll
    for (int nt = 0; nt < 4; nt++) {
        int cg = col0 + wn * 32 + nt * 8 + 2 * (lane & 3);
        float b0 = bias[cg], b1 = bias[cg + 1];
#pragma unroll
        for (int mt = 0; mt < 4; mt++) {
            int r0 = m0 + wm * 64 + mt * 16 + (lane >> 2);
            if (r0 < NN) {
                float2 o;
                o.x = fmaxf(acc[mt][nt][0] + b0, 0.f);
                o.y = fmaxf(acc[mt][nt][1] + b1, 0.f);
                *(float2*)(g_H1 + (size_t)r0 * NH + cg) = o;
            }
            int r1 = r0 + 8;
            if (r1 < NN) {
                float2 o;
                o.x = fmaxf(acc[mt][nt][2] + b0, 0.f);
                o.y = fmaxf(acc[mt][nt][3] + b1, 0.f);
                *(float2*)(g_H1 + (size_t)r1 * NH + cg) = o;
            }
        }
    }
}

// ---------------- GEMM2 + epilogue: h = H1 @ W2 + b2; q0 = d*h; TH = t0*h ---
__global__ __launch_bounds__(256) void gemm2_kernel(const float* __restrict__ W2,
                                                    const float* __restrict__ b2,
                                                    const float* __restrict__ temp) {
    __shared__ float4 W2s[NH * 10];
    __shared__ float  b2s[NC];
    int tid = threadIdx.x;
    for (int i = tid; i < NH * 10; i += 256) W2s[i] = ((const float4*)W2)[i];
    if (tid < NC) b2s[tid] = b2[tid];
    __syncthreads();

    int v = blockIdx.x * 256 + tid;
    if (v >= NN) return;

    float acc[NC];
#pragma unroll
    for (int c = 0; c < NC; c++) acc[c] = 0.f;

    const float4* hrow = (const float4*)(g_H1 + (size_t)v * NH);
#pragma unroll 2
    for (int k4 = 0; k4 < NH / 4; k4++) {
        float4 a = hrow[k4];
        const float4* wr = &W2s[(k4 * 4) * 10];
        float av[4] = {a.x, a.y, a.z, a.w};
#pragma unroll
        for (int kk = 0; kk < 4; kk++) {
#pragma unroll
            for (int c4 = 0; c4 < 10; c4++) {
                float4 w = wr[kk * 10 + c4];
                acc[c4 * 4 + 0] += av[kk] * w.x;
                acc[c4 * 4 + 1] += av[kk] * w.y;
                acc[c4 * 4 + 2] += av[kk] * w.z;
                acc[c4 * 4 + 3] += av[kk] * w.w;
            }
        }
    }

    float dv = g_d[v];
    float t0 = temp[0];
    float4* qrow = g_q0 + v * 10;
    float4* trow = g_TH + v * 10;
#pragma unroll
    for (int c4 = 0; c4 < 10; c4++) {
        float hx = acc[c4 * 4 + 0] + b2s[c4 * 4 + 0];
        float hy = acc[c4 * 4 + 1] + b2s[c4 * 4 + 1];
        float hz = acc[c4 * 4 + 2] + b2s[c4 * 4 + 2];
        float hw = acc[c4 * 4 + 3] + b2s[c4 * 4 + 3];
        qrow[c4] = make_float4(dv * hx, dv * hy, dv * hz, dv * hw);
        trow[c4] = make_float4(t0 * hx, t0 * hy, t0 * hz, t0 * hw);
    }
}

// ---------------- one propagation hop ---------------------------------------
__global__ void hop_kernel(const float* __restrict__ temp, int hop) {
    int t  = blockIdx.x * blockDim.x + threadIdx.x;
    int v  = t >> 4;
    int c4 = t & 15;
    if (v >= NN || c4 >= 10) return;

    const float4* qin = (hop & 1) ? g_q1 : g_q0;
    float4*       qout = (hop & 1) ? g_q0 : g_q1;

    int rs = g_rowptr[v];
    int re = g_rowptr[v + 1];
    float4 acc = qin[v * 10 + c4];

    int i = rs;
    for (; i + 1 < re; i += 2) {
        int u0 = g_col[i];
        int u1 = g_col[i + 1];
        float4 x0 = qin[u0 * 10 + c4];
        float4 x1 = qin[u1 * 10 + c4];
        acc.x += x0.x; acc.y += x0.y; acc.z += x0.z; acc.w += x0.w;
        acc.x += x1.x; acc.y += x1.y; acc.z += x1.z; acc.w += x1.w;
    }
    if (i < re) {
        int u = g_col[i];
        float4 x = qin[u * 10 + c4];
        acc.x += x.x; acc.y += x.y; acc.z += x.z; acc.w += x.w;
    }

    float dv = g_d[v];
    float tk = temp[hop + 1];
    float dd = dv * dv;
    float td = tk * dv;

    qout[v * 10 + c4] = make_float4(dd * acc.x, dd * acc.y, dd * acc.z, dd * acc.w);
    float4 th = g_TH[v * 10 + c4];
    g_TH[v * 10 + c4] = make_float4(th.x + td * acc.x, th.y + td * acc.y,
                                    th.z + td * acc.z, th.w + td * acc.w);
}

// ---------------- log_softmax epilogue ---------------------------------------
__global__ void final_kernel(float* __restrict__ out) {
    int v = blockIdx.x * blockDim.x + threadIdx.x;
    if (v >= NN) return;
    float th[NC];
    const float4* trow = g_TH + v * 10;
#pragma unroll
    for (int c4 = 0; c4 < 10; c4++) {
        float4 x = trow[c4];
        th[c4 * 4 + 0] = x.x;
        th[c4 * 4 + 1] = x.y;
        th[c4 * 4 + 2] = x.z;
        th[c4 * 4 + 3] = x.w;
    }
    float m = th[0];
#pragma unroll
    for (int c = 1; c < NC; c++) m = fmaxf(m, th[c]);
    float s = 0.f;
#pragma unroll
    for (int c = 0; c < NC; c++) s += __expf(th[c] - m);
    float lse = m + logf(s);
    float4* orow = (float4*)(out + (size_t)v * NC);
#pragma unroll
    for (int c4 = 0; c4 < 10; c4++) {
        orow[c4] = make_float4(th[c4 * 4 + 0] - lse, th[c4 * 4 + 1] - lse,
                               th[c4 * 4 + 2] - lse, th[c4 * 4 + 3] - lse);
    }
}

// ---------------- launch -----------------------------------------------------
extern "C" void kernel_launch(void* const* d_in, const int* in_sizes, int n_in,
                              void* d_out, int out_size) {
    (void)in_sizes; (void)n_in; (void)out_size;
    const float* feat = (const float*)d_in[0];
    const float* W1   = (const float*)d_in[1];
    const float* b1   = (const float*)d_in[2];
    const float* W2   = (const float*)d_in[3];
    const float* b2   = (const float*)d_in[4];
    const float* temp = (const float*)d_in[5];
    const int*   src  = (const int*)d_in[6];
    const int*   dst  = (const int*)d_in[7];
    float* out = (float*)d_out;

    zero_deg_kernel<<<(NN + 255) / 256, 256>>>();
    count_deg_kernel<<<(NE + 255) / 256, 256>>>(dst);
    scan_kernel<<<1, 1024>>>();
    scatter_kernel<<<(NE + 255) / 256, 256>>>(src, dst);

    prep_w1_kernel<<<(NH * NF + 255) / 256, 256>>>(W1);
    gemm1_mma_kernel<<<dim3(NH / 128, (NN + 127) / 128), 256>>>(feat, b1);
    gemm2_kernel<<<(NN + 255) / 256, 256>>>(W2, b2, temp);

    for (int k = 0; k < KH; k++) {
        hop_kernel<<<(NN * 16 + 255) / 256, 256>>>(temp, k);
    }

    final_kernel<<<(NN + 255) / 256, 256>>>(out);
}

// round 17
// speedup vs baseline: 1.0332x; 1.0005x over previous
#include <cuda_runtime.h>
#include <cuda_fp16.h>
#include <cstdint>

#define NN 100000
#define NF 512
#define NH 256
#define NC 40
#define NE 1600000
#define KH 10

// ---------------- scratch (device globals; no allocations allowed) ----------
__device__ float  g_H1[(size_t)NN * NH];   // hidden activations (102.4 MB)
__device__ float4 g_q0[NN * 10];           // q = d*h, ping      (16 MB)
__device__ float4 g_q1[NN * 10];           // q pong             (16 MB)
__device__ float4 g_TH[NN * 10];           // accumulated logits (16 MB)
__device__ int    g_deg[NN];
__device__ float  g_d[NN];
__device__ int    g_rowptr[NN + 1];
__device__ int    g_cursor[NN];
__device__ int    g_col[NE];
// W1 split to fp16 hi/lo, transposed to [n=256][k=512] (k contiguous)
__device__ __align__(16) __half g_Bhi[NH * NF];
__device__ __align__(16) __half g_Blo[NH * NF];

// ---------------- graph preprocessing ---------------------------------------
__global__ void zero_deg_kernel() {
    int v = blockIdx.x * blockDim.x + threadIdx.x;
    if (v < NN) g_deg[v] = 0;
}
__global__ void count_deg_kernel(const int* __restrict__ dst) {
    int e = blockIdx.x * blockDim.x + threadIdx.x;
    if (e < NE) atomicAdd(&g_deg[dst[e]], 1);
}
__global__ void scan_kernel() {
    const int T = 1024;
    int tid = threadIdx.x;
    const int per = (NN + T - 1) / T;
    int base = tid * per;
    int s = 0;
    for (int i = 0; i < per; i++) {
        int v = base + i;
        if (v < NN) s += g_deg[v];
    }
    __shared__ int sm[T];
    sm[tid] = s;
    __syncthreads();
    for (int off = 1; off < T; off <<= 1) {
        int add = (tid >= off) ? sm[tid - off] : 0;
        __syncthreads();
        sm[tid] += add;
        __syncthreads();
    }
    int run = sm[tid] - s;
    for (int i = 0; i < per; i++) {
        int v = base + i;
        if (v < NN) {
            int dv = g_deg[v];
            g_rowptr[v] = run;
            g_cursor[v] = run;
            g_d[v] = rsqrtf((float)(dv + 1));
            run += dv;
        }
    }
    if (tid == T - 1) g_rowptr[NN] = run;
}
__global__ void scatter_kernel(const int* __restrict__ src, const int* __restrict__ dst) {
    int e = blockIdx.x * blockDim.x + threadIdx.x;
    if (e < NE) {
        int v = dst[e];
        int p = atomicAdd(&g_cursor[v], 1);
        g_col[p] = src[e];
    }
}

// ---------------- W1 -> transposed fp16 hi/lo images -------------------------
__global__ void prep_w1_kernel(const float* __restrict__ W1) {
    int t = blockIdx.x * blockDim.x + threadIdx.x;
    if (t >= NH * NF) return;
    int k = t & (NF - 1);
    int n = t >> 9;
    float x = W1[(size_t)k * NH + n];
    __half h = __float2half_rn(x);
    float lo = x - __half2float(h);
    g_Bhi[(size_t)n * NF + k] = h;
    g_Blo[(size_t)n * NF + k] = __float2half_rn(lo);
}

// ---------------- GEMM1 on mma.sync fp16 (2-pass asymmetric split) ----------
// H1 = relu(feat @ W1 + b1). CTA 128(M) x 128(N), BK=32, 8 warps @ 64x32.
#define BK 32
#define RSTR 20  // smem row stride in uints (80 B): conflict-free frag loads

__device__ __forceinline__ void mma16816(float* c, const uint32_t* a, const uint32_t* b) {
    asm volatile(
        "mma.sync.aligned.m16n8k16.row.col.f32.f16.f16.f32 "
        "{%0,%1,%2,%3}, {%4,%5,%6,%7}, {%8,%9}, {%0,%1,%2,%3};"
        : "+f"(c[0]), "+f"(c[1]), "+f"(c[2]), "+f"(c[3])
        : "r"(a[0]), "r"(a[1]), "r"(a[2]), "r"(a[3]), "r"(b[0]), "r"(b[1]));
}

__global__ __launch_bounds__(256, 2) void gemm1_mma_kernel(const float* __restrict__ A,
                                                           const float* __restrict__ bias) {
    __shared__ uint32_t sA [128 * RSTR];
    __shared__ uint32_t sBh[128 * RSTR];
    __shared__ uint32_t sBl[128 * RSTR];

    const int tid = threadIdx.x;
    const int wid = tid >> 5, lane = tid & 31;
    const int wm = wid >> 2, wn = wid & 3;        // warp tile: (wm*64, wn*32)
    const int m0 = blockIdx.y * 128;
    const int col0 = blockIdx.x * 128;

    float acc[4][4][4];
#pragma unroll
    for (int i = 0; i < 4; i++)
#pragma unroll
        for (int j = 0; j < 4; j++)
#pragma unroll
            for (int e = 0; e < 4; e++) acc[i][j][e] = 0.f;

    // per-thread staging indices: row lr = tid>>1, k-half seg = tid&1 (16 elems)
    const int lr = tid >> 1, seg = tid & 1;
    const int gr = m0 + lr;
    const bool avalid = gr < NN;
    const float* Arow = A + (size_t)gr * NF + seg * 16;
    const __half* BHrow = g_Bhi + (size_t)(col0 + lr) * NF + seg * 16;
    const __half* BLrow = g_Blo + (size_t)(col0 + lr) * NF + seg * 16;
    const int sbase = lr * RSTR + seg * 8;

    for (int kc = 0; kc < NF / BK; kc++) {
        __syncthreads();
        // ---- stage A: fp32 -> fp16 (single rounding)
        {
            float vals[16];
            if (avalid) {
#pragma unroll
                for (int q = 0; q < 4; q++) {
                    float4 v = *(const float4*)(Arow + kc * BK + q * 4);
                    vals[q * 4 + 0] = v.x; vals[q * 4 + 1] = v.y;
                    vals[q * 4 + 2] = v.z; vals[q * 4 + 3] = v.w;
                }
            } else {
#pragma unroll
                for (int q = 0; q < 16; q++) vals[q] = 0.f;
            }
            uint32_t hu[8];
#pragma unroll
            for (int p = 0; p < 8; p++) {
                __half h0 = __float2half_rn(vals[2 * p]);
                __half h1 = __float2half_rn(vals[2 * p + 1]);
                hu[p] = (uint32_t)__half_as_ushort(h0) |
                        ((uint32_t)__half_as_ushort(h1) << 16);
            }
            *(uint4*)&sA[sbase]     = make_uint4(hu[0], hu[1], hu[2], hu[3]);
            *(uint4*)&sA[sbase + 4] = make_uint4(hu[4], hu[5], hu[6], hu[7]);
        }
        // ---- stage B: copy pre-split fp16 (L2-hot)
        {
            const uint4* ph = (const uint4*)(BHrow + kc * BK);
            const uint4* pl = (const uint4*)(BLrow + kc * BK);
            *(uint4*)&sBh[sbase]     = ph[0];
            *(uint4*)&sBh[sbase + 4] = ph[1];
            *(uint4*)&sBl[sbase]     = pl[0];
            *(uint4*)&sBl[sbase + 4] = pl[1];
        }
        __syncthreads();

        // ---- compute: 2 k16 steps x 2 passes (A x Bhi, A x Blo); A frags reused
#pragma unroll
        for (int k16 = 0; k16 < 2; k16++) {
            uint32_t af[4][4];
#pragma unroll
            for (int mt = 0; mt < 4; mt++) {
                int r = wm * 64 + mt * 16 + (lane >> 2);
                int b = r * RSTR + k16 * 8 + (lane & 3);
                af[mt][0] = sA[b];
                af[mt][1] = sA[b + 8 * RSTR];
                af[mt][2] = sA[b + 4];
                af[mt][3] = sA[b + 8 * RSTR + 4];
            }
            uint32_t bf_[4][2];
#pragma unroll
            for (int nt = 0; nt < 4; nt++) {
                int n = wn * 32 + nt * 8 + (lane >> 2);
                int b = n * RSTR + k16 * 8 + (lane & 3);
                bf_[nt][0] = sBh[b];
                bf_[nt][1] = sBh[b + 4];
            }
#pragma unroll
            for (int mt = 0; mt < 4; mt++)
#pragma unroll
                for (int nt = 0; nt < 4; nt++)
                    mma16816(acc[mt][nt], af[mt], bf_[nt]);
#pragma unroll
            for (int nt = 0; nt < 4; nt++) {
                int n = wn * 32 + nt * 8 + (lane >> 2);
                int b = n * RSTR + k16 * 8 + (lane & 3);
                bf_[nt][0] = sBl[b];
                bf_[nt][1] = sBl[b + 4];
            }
#pragma unroll
            for (int mt = 0; mt < 4; mt++)
#pragma unroll
                for (int nt = 0; nt < 4; nt++)
                    mma16816(acc[mt][nt], af[mt], bf_[nt]);
        }
    }

    // ---- epilogue: bias + relu, store fp32
#pragma unroll
    for (int nt = 0; nt < 4; nt++) {
        int cg = col0 + wn * 32 + nt * 8 + 2 * (lane & 3);
        float b0 = bias[cg], b1 = bias[cg + 1];
#pragma unroll
        for (int mt = 0; mt < 4; mt++) {
            int r0 = m0 + wm * 64 + mt * 16 + (lane >> 2);
            if (r0 < NN) {
                float2 o;
                o.x = fmaxf(acc[mt][nt][0] + b0, 0.f);
                o.y = fmaxf(acc[mt][nt][1] + b1, 0.f);
                *(float2*)(g_H1 + (size_t)r0 * NH + cg) = o;
            }
            int r1 = r0 + 8;
            if (r1 < NN) {
                float2 o;
                o.x = fmaxf(acc[mt][nt][2] + b0, 0.f);
                o.y = fmaxf(acc[mt][nt][3] + b1, 0.f);
                *(float2*)(g_H1 + (size_t)r1 * NH + cg) = o;
            }
        }
    }
}

// ---------------- GEMM2 + epilogue: h = H1 @ W2 + b2; q0 = d*h; TH = t0*h ---
__global__ __launch_bounds__(256) void gemm2_kernel(const float* __restrict__ W2,
                                                    const float* __restrict__ b2,
                                                    const float* __restrict__ temp) {
    __shared__ float4 W2s[NH * 10];
    __shared__ float  b2s[NC];
    int tid = threadIdx.x;
    for (int i = tid; i < NH * 10; i += 256) W2s[i] = ((const float4*)W2)[i];
    if (tid < NC) b2s[tid] = b2[tid];
    __syncthreads();

    int v = blockIdx.x * 256 + tid;
    if (v >= NN) return;

    float acc[NC];
#pragma unroll
    for (int c = 0; c < NC; c++) acc[c] = 0.f;

    const float4* hrow = (const float4*)(g_H1 + (size_t)v * NH);
#pragma unroll 2
    for (int k4 = 0; k4 < NH / 4; k4++) {
        float4 a = hrow[k4];
        const float4* wr = &W2s[(k4 * 4) * 10];
        float av[4] = {a.x, a.y, a.z, a.w};
#pragma unroll
        for (int kk = 0; kk < 4; kk++) {
#pragma unroll
            for (int c4 = 0; c4 < 10; c4++) {
                float4 w = wr[kk * 10 + c4];
                acc[c4 * 4 + 0] += av[kk] * w.x;
                acc[c4 * 4 + 1] += av[kk] * w.y;
                acc[c4 * 4 + 2] += av[kk] * w.z;
                acc[c4 * 4 + 3] += av[kk] * w.w;
            }
        }
    }

    float dv = g_d[v];
    float t0 = temp[0];
    float4* qrow = g_q0 + v * 10;
    float4* trow = g_TH + v * 10;
#pragma unroll
    for (int c4 = 0; c4 < 10; c4++) {
        float hx = acc[c4 * 4 + 0] + b2s[c4 * 4 + 0];
        float hy = acc[c4 * 4 + 1] + b2s[c4 * 4 + 1];
        float hz = acc[c4 * 4 + 2] + b2s[c4 * 4 + 2];
        float hw = acc[c4 * 4 + 3] + b2s[c4 * 4 + 3];
        qrow[c4] = make_float4(dv * hx, dv * hy, dv * hz, dv * hw);
        trow[c4] = make_float4(t0 * hx, t0 * hy, t0 * hz, t0 * hw);
    }
}

// ---------------- one propagation hop ---------------------------------------
__global__ void hop_kernel(const float* __restrict__ temp, int hop) {
    int t  = blockIdx.x * blockDim.x + threadIdx.x;
    int v  = t >> 4;
    int c4 = t & 15;
    if (v >= NN || c4 >= 10) return;

    const float4* qin = (hop & 1) ? g_q1 : g_q0;
    float4*       qout = (hop & 1) ? g_q0 : g_q1;

    int rs = g_rowptr[v];
    int re = g_rowptr[v + 1];
    float4 acc = qin[v * 10 + c4];

    int i = rs;
    for (; i + 1 < re; i += 2) {
        int u0 = g_col[i];
        int u1 = g_col[i + 1];
        float4 x0 = qin[u0 * 10 + c4];
        float4 x1 = qin[u1 * 10 + c4];
        acc.x += x0.x; acc.y += x0.y; acc.z += x0.z; acc.w += x0.w;
        acc.x += x1.x; acc.y += x1.y; acc.z += x1.z; acc.w += x1.w;
    }
    if (i < re) {
        int u = g_col[i];
        float4 x = qin[u * 10 + c4];
        acc.x += x.x; acc.y += x.y; acc.z += x.z; acc.w += x.w;
    }

    float dv = g_d[v];
    float tk = temp[hop + 1];
    float dd = dv * dv;
    float td = tk * dv;

    qout[v * 10 + c4] = make_float4(dd * acc.x, dd * acc.y, dd * acc.z, dd * acc.w);
    float4 th = g_TH[v * 10 + c4];
    g_TH[v * 10 + c4] = make_float4(th.x + td * acc.x, th.y + td * acc.y,
                                    th.z + td * acc.z, th.w + td * acc.w);
}

// ---------------- log_softmax epilogue ---------------------------------------
__global__ void final_kernel(float* __restrict__ out) {
    int v = blockIdx.x * blockDim.x + threadIdx.x;
    if (v >= NN) return;
    float th[NC];
    const float4* trow = g_TH + v * 10;
#pragma unroll
    for (int c4 = 0; c4 < 10; c4++) {
        float4 x = trow[c4];
        th[c4 * 4 + 0] = x.x;
        th[c4 * 4 + 1] = x.y;
        th[c4 * 4 + 2] = x.z;
        th[c4 * 4 + 3] = x.w;
    }
    float m = th[0];
#pragma unroll
    for (int c = 1; c < NC; c++) m = fmaxf(m, th[c]);
    float s = 0.f;
#pragma unroll
    for (int c = 0; c < NC; c++) s += __expf(th[c] - m);
    float lse = m + logf(s);
    float4* orow = (float4*)(out + (size_t)v * NC);
#pragma unroll
    for (int c4 = 0; c4 < 10; c4++) {
        orow[c4] = make_float4(th[c4 * 4 + 0] - lse, th[c4 * 4 + 1] - lse,
                               th[c4 * 4 + 2] - lse, th[c4 * 4 + 3] - lse);
    }
}

// ---------------- launch -----------------------------------------------------
extern "C" void kernel_launch(void* const* d_in, const int* in_sizes, int n_in,
                              void* d_out, int out_size) {
    (void)in_sizes; (void)n_in; (void)out_size;
    const float* feat = (const float*)d_in[0];
    const float* W1   = (const float*)d_in[1];
    const float* b1   = (const float*)d_in[2];
    const float* W2   = (const float*)d_in[3];
    const float* b2   = (const float*)d_in[4];
    const float* temp = (const float*)d_in[5];
    const int*   src  = (const int*)d_in[6];
    const int*   dst  = (const int*)d_in[7];
    float* out = (float*)d_out;

    zero_deg_kernel<<<(NN + 255) / 256, 256>>>();
    count_deg_kernel<<<(NE + 255) / 256, 256>>>(dst);
    scan_kernel<<<1, 1024>>>();
    scatter_kernel<<<(NE + 255) / 256, 256>>>(src, dst);

    prep_w1_kernel<<<(NH * NF + 255) / 256, 256>>>(W1);
    gemm1_mma_kernel<<<dim3(NH / 128, (NN + 127) / 128), 256>>>(feat, b1);
    gemm2_kernel<<<(NN + 255) / 256, 256>>>(W2, b2, temp);

    for (int k = 0; k < KH; k++) {
        hop_kernel<<<(NN * 16 + 255) / 256, 256>>>(temp, k);
    }

    final_kernel<<<(NN + 255) / 256, 256>>>(out);
}